// round 6
// baseline (speedup 1.0000x reference)
#include <cuda_runtime.h>
#include <cuda_fp16.h>
#include <cstdint>

#define N_FRAMES 65536
#define H_DIM    512
#define GVDIM    640
#define VNUM     320
#define DDIM     128

// --------------------------- device scratch --------------------------------
__device__ float g_logits[(size_t)N_FRAMES * GVDIM];   // 160 MiB
__device__ float g_marginal[GVDIM];
__device__ __half g_B0[GVDIM * H_DIM];                 // W^T split hi [640][512]
__device__ __half g_B1[GVDIM * H_DIM];                 // W^T split lo

// --------------------------- helpers ---------------------------------------
__device__ __forceinline__ uint32_t smem_u32(const void* p) {
    uint32_t a;
    asm("{ .reg .u64 t; cvta.to.shared.u64 t, %1; cvt.u32.u64 %0, t; }"
        : "=r"(a) : "l"(p));
    return a;
}

__device__ __forceinline__ void cp_async16(uint32_t saddr, const void* gaddr) {
    asm volatile("cp.async.cg.shared.global [%0], [%1], 16;"
                 :: "r"(saddr), "l"(gaddr) : "memory");
}

__device__ __forceinline__ void ldsm4(uint32_t r[4], uint32_t addr) {
    asm volatile("ldmatrix.sync.aligned.m8n8.x4.shared.b16 {%0,%1,%2,%3}, [%4];"
                 : "=r"(r[0]), "=r"(r[1]), "=r"(r[2]), "=r"(r[3]) : "r"(addr));
}

__device__ __forceinline__ void mma16816(float c[4], const uint32_t a[4],
                                         const uint32_t b[2]) {
    asm volatile(
        "mma.sync.aligned.m16n8k16.row.col.f32.f16.f16.f32 "
        "{%0,%1,%2,%3}, {%4,%5,%6,%7}, {%8,%9}, {%0,%1,%2,%3};"
        : "+f"(c[0]), "+f"(c[1]), "+f"(c[2]), "+f"(c[3])
        : "r"(a[0]), "r"(a[1]), "r"(a[2]), "r"(a[3]), "r"(b[0]), "r"(b[1]));
}

__device__ __forceinline__ uint32_t pack_h2(float a, float b) {
    __half2 h = __floats2half2_rn(a, b);
    return *reinterpret_cast<uint32_t*>(&h);
}
__device__ __forceinline__ float2 unpack_h2(uint32_t w) {
    __half2 h = *reinterpret_cast<__half2*>(&w);
    return __half22float2(h);
}

// ---------------------------------------------------------------------------
// ~1-ulp log (fast-math proof)
// ---------------------------------------------------------------------------
__device__ __forceinline__ float acc_logf(float x) {
    int   ix = __float_as_int(x);
    int   e  = ((ix >> 23) & 0xff) - 126;
    float m  = __int_as_float((ix & 0x007fffff) | 0x3f000000);
    if (m < 0.70710678118654752f) { m += m; e -= 1; }
    float f = m - 1.0f;
    float z = f * f;
    float p = 7.0376836292e-2f;
    p = fmaf(p, f, -1.1514610310e-1f);
    p = fmaf(p, f,  1.1676998740e-1f);
    p = fmaf(p, f, -1.2420140846e-1f);
    p = fmaf(p, f,  1.4249322787e-1f);
    p = fmaf(p, f, -1.6668057665e-1f);
    p = fmaf(p, f,  2.0000714765e-1f);
    p = fmaf(p, f, -2.4999993993e-1f);
    p = fmaf(p, f,  3.3333331174e-1f);
    p = p * f * z;
    float ef = (float)e;
    p = fmaf(-0.5f, z, p);
    float r = fmaf(ef, -2.12194440e-4f, p);
    r = r + f;
    r = fmaf(ef, 0.693359375f, r);
    return r;
}

// ---------------------------------------------------------------------------
// W[k][n] -> B[n][k] fp16 2-way split; also zeroes g_marginal
// ---------------------------------------------------------------------------
__global__ __launch_bounds__(512) void split_b_kernel(const float* __restrict__ W) {
    int n = blockIdx.x;       // 0..639
    int k = threadIdx.x;      // 0..511
    if (k == 0) g_marginal[n] = 0.0f;
    float v = W[(size_t)k * GVDIM + n];
    __half h0 = __float2half_rn(v);
    __half h1 = __float2half_rn(v - __half2float(h0));
    g_B0[(size_t)n * H_DIM + k] = h0;
    g_B1[(size_t)n * H_DIM + k] = h1;
}

// ---------------------------------------------------------------------------
// GEMM with fused A split: logits = A*W + b, 3-term fp16 (a0b0+a0b1+a1b0).
// BM=128, BN=128, BK=32; 256 threads; warp tile 64x32.
// smem: A32 staging (2 bufs) + A16 splits (single) + B splits (2 bufs).
// ---------------------------------------------------------------------------
#define A32_BYTES   20480          // 256 threads x 80B pitch
#define SPLIT_BYTES 10240          // 128 rows x 80B
#define A16_OFF     (2 * A32_BYTES)              // 40960
#define B_OFF       (A16_OFF + 2 * SPLIT_BYTES)  // 61440
#define B_STG       20480
#define SMEM_BYTES  (B_OFF + 2 * B_STG)          // 102400

__global__ __launch_bounds__(256, 2) void gemm_kernel(
    const float* __restrict__ A, const float* __restrict__ bias)
{
    extern __shared__ char smem[];
    const uint32_t sb = smem_u32(smem);
    const int tid  = threadIdx.x;
    const int wid  = tid >> 5;
    const int lane = tid & 31;
    const int wm = wid >> 2;           // 0..1
    const int wn = wid & 3;            // 0..3
    const int m0 = blockIdx.y * 128;
    const int n0 = blockIdx.x * 128;

    float acc[4][4][4];
#pragma unroll
    for (int mf = 0; mf < 4; mf++)
#pragma unroll
        for (int nf = 0; nf < 4; nf++)
#pragma unroll
            for (int c = 0; c < 4; c++) acc[mf][nf][c] = 0.0f;

    // ---- A fp32 loader: thread owns row=tid&127, half=tid>>7 (16 floats) ----
    const int crow  = tid & 127;
    const int chalf = tid >> 7;
    const float* gA = A + (size_t)(m0 + crow) * H_DIM + chalf * 16;
    const uint32_t a32dst = sb + tid * 80;

    // ---- B loader: thread owns rows r0,r0+64 of both splits, chunk kc ----
    const int r0 = tid >> 2;
    const int kc = tid & 3;
    const __half* pB0 = g_B0 + (size_t)(n0 + r0) * H_DIM + kc * 8;
    const __half* pB1 = g_B1 + (size_t)(n0 + r0) * H_DIM + kc * 8;
    const uint32_t sB = sb + B_OFF + r0 * 80 + kc * 16;
    const size_t ROW64 = (size_t)64 * H_DIM;

    auto issue_stage = [&](int s) {
        const int off = s * 32;                  // element offset in k
        const uint32_t abuf = (uint32_t)(s & 1) * A32_BYTES;
#pragma unroll
        for (int c = 0; c < 4; c++)
            cp_async16(a32dst + abuf + c * 16, gA + off + c * 4);
        const uint32_t bbuf = (uint32_t)(s & 1) * B_STG;
        cp_async16(sB + bbuf,                pB0 + off);
        cp_async16(sB + bbuf + 5120,         pB0 + off + ROW64);
        cp_async16(sB + bbuf + SPLIT_BYTES,        pB1 + off);
        cp_async16(sB + bbuf + SPLIT_BYTES + 5120, pB1 + off + ROW64);
        asm volatile("cp.async.commit_group;" ::: "memory");
    };

    issue_stage(0);

    const int a_row = wm * 64 + (lane & 15);
    const int a_kc  = (lane >> 4) * 16;
    const int b_row = wn * 32 + ((lane >> 4) & 1) * 8 + (lane & 7);
    const int b_kc  = ((lane >> 3) & 1) * 16;
    const uint32_t a16base = sb + A16_OFF;

    char* const a32rd  = smem + tid * 80;
    char* const a16wr0 = smem + A16_OFF + crow * 80 + chalf * 32;
    char* const a16wr1 = a16wr0 + SPLIT_BYTES;

    for (int s = 0; s < 16; s++) {
        asm volatile("cp.async.wait_group 0;" ::: "memory");
        __syncthreads();                   // cp data visible; prior ldsm done
        if (s + 1 < 16) issue_stage(s + 1);

        // ---- convert fp32 -> fp16 hi/lo splits (own data only) ----
        {
            const char* src = a32rd + (s & 1) * A32_BYTES;
            float4 f0 = *reinterpret_cast<const float4*>(src);
            float4 f1 = *reinterpret_cast<const float4*>(src + 16);
            float4 f2 = *reinterpret_cast<const float4*>(src + 32);
            float4 f3 = *reinterpret_cast<const float4*>(src + 48);
            float v[16] = {f0.x, f0.y, f0.z, f0.w, f1.x, f1.y, f1.z, f1.w,
                           f2.x, f2.y, f2.z, f2.w, f3.x, f3.y, f3.z, f3.w};
            uint32_t w0[8], w1[8];
#pragma unroll
            for (int i = 0; i < 8; i++) {
                const float a = v[2 * i], b = v[2 * i + 1];
                w0[i] = pack_h2(a, b);
                float2 bb = unpack_h2(w0[i]);
                w1[i] = pack_h2(a - bb.x, b - bb.y);
            }
            *reinterpret_cast<uint4*>(a16wr0)      = make_uint4(w0[0], w0[1], w0[2], w0[3]);
            *reinterpret_cast<uint4*>(a16wr0 + 16) = make_uint4(w0[4], w0[5], w0[6], w0[7]);
            *reinterpret_cast<uint4*>(a16wr1)      = make_uint4(w1[0], w1[1], w1[2], w1[3]);
            *reinterpret_cast<uint4*>(a16wr1 + 16) = make_uint4(w1[4], w1[5], w1[6], w1[7]);
        }
        __syncthreads();                   // A16 visible to all warps

        const uint32_t bbase = sb + B_OFF + (s & 1) * B_STG;

#pragma unroll
        for (int ks = 0; ks < 2; ks++) {
            uint32_t Bf[2][8];
#pragma unroll
            for (int s2 = 0; s2 < 2; s2++)
#pragma unroll
                for (int p = 0; p < 2; p++)
                    ldsm4(&Bf[s2][p * 4], bbase + s2 * SPLIT_BYTES +
                          (b_row + p * 16) * 80 + ks * 32 + b_kc);

            uint32_t Af[4][4];
#pragma unroll
            for (int mf = 0; mf < 4; mf++)
                ldsm4(Af[mf], a16base + (a_row + mf * 16) * 80 + ks * 32 + a_kc);
#pragma unroll
            for (int mf = 0; mf < 4; mf++)
#pragma unroll
                for (int nf = 0; nf < 4; nf++)
                    mma16816(acc[mf][nf], Af[mf], &Bf[0][nf * 2]);
#pragma unroll
            for (int mf = 0; mf < 4; mf++)
#pragma unroll
                for (int nf = 0; nf < 4; nf++)
                    mma16816(acc[mf][nf], Af[mf], &Bf[1][nf * 2]);
#pragma unroll
            for (int mf = 0; mf < 4; mf++)
                ldsm4(Af[mf], a16base + SPLIT_BYTES + (a_row + mf * 16) * 80 + ks * 32 + a_kc);
#pragma unroll
            for (int mf = 0; mf < 4; mf++)
#pragma unroll
                for (int nf = 0; nf < 4; nf++)
                    mma16816(acc[mf][nf], Af[mf], &Bf[0][nf * 2]);
        }
    }

    // ---- store + bias ----
    const int gID = lane >> 2;
    const int tig = lane & 3;
    float2 bv[4];
#pragma unroll
    for (int nf = 0; nf < 4; nf++)
        bv[nf] = *reinterpret_cast<const float2*>(bias + n0 + wn * 32 + nf * 8 + tig * 2);

#pragma unroll
    for (int mf = 0; mf < 4; mf++) {
        const int m = m0 + wm * 64 + mf * 16 + gID;
#pragma unroll
        for (int nf = 0; nf < 4; nf++) {
            const int n = n0 + wn * 32 + nf * 8 + tig * 2;
            float2 v0 = {acc[mf][nf][0] + bv[nf].x, acc[mf][nf][1] + bv[nf].y};
            float2 v1 = {acc[mf][nf][2] + bv[nf].x, acc[mf][nf][3] + bv[nf].y};
            *reinterpret_cast<float2*>(g_logits + (size_t)m * GVDIM + n)       = v0;
            *reinterpret_cast<float2*>(g_logits + (size_t)(m + 8) * GVDIM + n) = v1;
        }
    }
}

// ---------------------------------------------------------------------------
// Epilogue: one warp per (n,g) pair; 32 pairs per warp; 512 blocks x 256 thr.
// Approx-filter argmax: cheap __logf pass, exact acc_logf only for candidates.
// ---------------------------------------------------------------------------
__global__ __launch_bounds__(256) void epilogue_kernel(
    const float* __restrict__ gumbel_u,
    const float* __restrict__ codevectors,
    float* __restrict__ out)
{
    const unsigned FULL = 0xffffffffu;
    __shared__ float smar[GVDIM];
    const int tid  = threadIdx.x;
    const int warp = blockIdx.x * 8 + (tid >> 5);
    const int lane = tid & 31;

    for (int i = tid; i < GVDIM; i += 256) smar[i] = 0.0f;
    __syncthreads();

    float macc[2][10];
#pragma unroll
    for (int g = 0; g < 2; g++)
#pragma unroll
        for (int j = 0; j < 10; j++) macc[g][j] = 0.0f;

    const int p0 = warp * 32;
    for (int i = 0; i < 32; i++) {
        const int p = p0 + i;
        const int n = p >> 1;
        const int g = p & 1;
        const float* lrow = g_logits + (size_t)n * GVDIM + g * VNUM;
        const float* urow = gumbel_u + (size_t)p * VNUM;

        float l[10], u[10], za[10];
#pragma unroll
        for (int jj = 0; jj < 5; jj++) {
            const int e0 = 2 * (lane + 32 * jj);
            float2 lf = *reinterpret_cast<const float2*>(lrow + e0);
            float2 uf = *reinterpret_cast<const float2*>(urow + e0);
            l[2 * jj] = lf.x; l[2 * jj + 1] = lf.y;
            u[2 * jj] = uf.x; u[2 * jj + 1] = uf.y;
        }

        float lmax = -3.4e38f, zax = -3.4e38f;
#pragma unroll
        for (int s = 0; s < 10; s++) {
            lmax = fmaxf(lmax, l[s]);
            const float t  = -__logf(u[s]);
            const float zv = l[s] - __logf(t);
            za[s] = zv;
            if (u[s] <= 0.99f) zax = fmaxf(zax, zv);
        }
#pragma unroll
        for (int off = 16; off; off >>= 1) {
            lmax = fmaxf(lmax, __shfl_xor_sync(FULL, lmax, off));
            zax  = fmaxf(zax,  __shfl_xor_sync(FULL, zax,  off));
        }
        const float thresh = zax - 1e-3f;

        float zbest = -3.4e38f;
        int   ibest = 0x7fffffff;
#pragma unroll
        for (int jj = 0; jj < 5; jj++)
#pragma unroll
            for (int q = 0; q < 2; q++) {
                const int s = 2 * jj + q;
                if (u[s] > 0.99f || za[s] >= thresh) {
                    const float te = -acc_logf(u[s]);
                    const float zv = l[s] - acc_logf(te);
                    const int v = 64 * jj + 2 * lane + q;
                    if (zv > zbest || (zv == zbest && v < ibest)) { zbest = zv; ibest = v; }
                }
            }
#pragma unroll
        for (int off = 16; off; off >>= 1) {
            const float zo = __shfl_xor_sync(FULL, zbest, off);
            const int   io = __shfl_xor_sync(FULL, ibest, off);
            if (zo > zbest || (zo == zbest && io < ibest)) { zbest = zo; ibest = io; }
        }

        float e[10];
        float ssum = 0.0f;
#pragma unroll
        for (int s = 0; s < 10; s++) { e[s] = __expf(l[s] - lmax); ssum += e[s]; }
#pragma unroll
        for (int off = 16; off; off >>= 1)
            ssum += __shfl_xor_sync(FULL, ssum, off);
        const float rs = 1.0f / ssum;
#pragma unroll
        for (int s = 0; s < 10; s++) macc[g][s] = fmaf(e[s], rs, macc[g][s]);

        const float4* cvp = reinterpret_cast<const float4*>(
            codevectors + ((size_t)(g * VNUM + ibest)) * DDIM);
        float4* op = reinterpret_cast<float4*>(out + (size_t)n * 256 + g * DDIM);
        op[lane] = cvp[lane];
    }

#pragma unroll
    for (int g = 0; g < 2; g++)
#pragma unroll
        for (int jj = 0; jj < 5; jj++)
#pragma unroll
            for (int q = 0; q < 2; q++)
                atomicAdd(&smar[g * VNUM + 64 * jj + 2 * lane + q], macc[g][2 * jj + q]);
    __syncthreads();
    for (int i = tid; i < GVDIM; i += 256)
        atomicAdd(&g_marginal[i], smar[i]);
}

// ---------------------------------------------------------------------------
__global__ void perp_kernel(float* __restrict__ out, int out_size) {
    __shared__ float red[2][2];
    const int i    = threadIdx.x;          // 0..63
    const int grp  = i >> 5;
    const int lane = i & 31;
    float part = 0.0f;
    for (int v = lane; v < VNUM; v += 32) {
        const float m = g_marginal[grp * VNUM + v] * (1.0f / (float)N_FRAMES);
        part += m * acc_logf(m + 1e-7f);
    }
#pragma unroll
    for (int off = 16; off; off >>= 1)
        part += __shfl_xor_sync(0xffffffffu, part, off);
    if (lane == 0) red[grp][0] = part;
    __syncthreads();
    if (i == 0) {
        const float perp = __expf(-red[0][0]) + __expf(-red[1][0]);
        if (out_size > N_FRAMES * 256) out[(size_t)N_FRAMES * 256] = perp;
    }
}

// ---------------------------------------------------------------------------
extern "C" void kernel_launch(void* const* d_in, const int* in_sizes, int n_in,
                              void* d_out, int out_size) {
    const float* hs = (const float*)d_in[0];   // [16,4096,512]
    const float* W  = (const float*)d_in[1];   // [512,640]
    const float* b  = (const float*)d_in[2];   // [640]
    const float* cv = (const float*)d_in[3];   // [640,128]
    const float* gu = (const float*)d_in[4];   // [131072,320]
    float* out = (float*)d_out;

    split_b_kernel<<<GVDIM, 512>>>(W);

    cudaFuncSetAttribute(gemm_kernel,
                         cudaFuncAttributeMaxDynamicSharedMemorySize, SMEM_BYTES);
    gemm_kernel<<<dim3(5, 512), 256, SMEM_BYTES>>>(hs, b);

    epilogue_kernel<<<512, 256>>>(gu, cv, out);
    perp_kernel<<<1, 64>>>(out, out_size);
}

// round 7
// speedup vs baseline: 1.1115x; 1.1115x over previous
#include <cuda_runtime.h>
#include <cuda_fp16.h>
#include <cstdint>

#define N_FRAMES 65536
#define H_DIM    512
#define GVDIM    640
#define VNUM     320
#define DDIM     128

// --------------------------- device scratch --------------------------------
__device__ float g_logits[(size_t)N_FRAMES * GVDIM];   // 160 MiB
__device__ float g_marginal[GVDIM];
__device__ __half g_A0[(size_t)N_FRAMES * H_DIM];      // 64 MiB
__device__ __half g_A1[(size_t)N_FRAMES * H_DIM];      // 64 MiB
__device__ __half g_B0[GVDIM * H_DIM];                 // W^T split hi [640][512]
__device__ __half g_B1[GVDIM * H_DIM];                 // W^T split lo

// --------------------------- helpers ---------------------------------------
__device__ __forceinline__ uint32_t smem_u32(const void* p) {
    uint32_t a;
    asm("{ .reg .u64 t; cvta.to.shared.u64 t, %1; cvt.u32.u64 %0, t; }"
        : "=r"(a) : "l"(p));
    return a;
}

__device__ __forceinline__ void cp_async16(uint32_t saddr, const void* gaddr) {
    asm volatile("cp.async.cg.shared.global [%0], [%1], 16;"
                 :: "r"(saddr), "l"(gaddr) : "memory");
}

__device__ __forceinline__ void ldsm4(uint32_t r[4], uint32_t addr) {
    asm volatile("ldmatrix.sync.aligned.m8n8.x4.shared.b16 {%0,%1,%2,%3}, [%4];"
                 : "=r"(r[0]), "=r"(r[1]), "=r"(r[2]), "=r"(r[3]) : "r"(addr));
}

__device__ __forceinline__ void mma16816(float c[4], const uint32_t a[4],
                                         const uint32_t b[2]) {
    asm volatile(
        "mma.sync.aligned.m16n8k16.row.col.f32.f16.f16.f32 "
        "{%0,%1,%2,%3}, {%4,%5,%6,%7}, {%8,%9}, {%0,%1,%2,%3};"
        : "+f"(c[0]), "+f"(c[1]), "+f"(c[2]), "+f"(c[3])
        : "r"(a[0]), "r"(a[1]), "r"(a[2]), "r"(a[3]), "r"(b[0]), "r"(b[1]));
}

// ---------------------------------------------------------------------------
// ~1-ulp log (fast-math proof)
// ---------------------------------------------------------------------------
__device__ __forceinline__ float acc_logf(float x) {
    int   ix = __float_as_int(x);
    int   e  = ((ix >> 23) & 0xff) - 126;
    float m  = __int_as_float((ix & 0x007fffff) | 0x3f000000);
    if (m < 0.70710678118654752f) { m += m; e -= 1; }
    float f = m - 1.0f;
    float z = f * f;
    float p = 7.0376836292e-2f;
    p = fmaf(p, f, -1.1514610310e-1f);
    p = fmaf(p, f,  1.1676998740e-1f);
    p = fmaf(p, f, -1.2420140846e-1f);
    p = fmaf(p, f,  1.4249322787e-1f);
    p = fmaf(p, f, -1.6668057665e-1f);
    p = fmaf(p, f,  2.0000714765e-1f);
    p = fmaf(p, f, -2.4999993993e-1f);
    p = fmaf(p, f,  3.3333331174e-1f);
    p = p * f * z;
    float ef = (float)e;
    p = fmaf(-0.5f, z, p);
    float r = fmaf(ef, -2.12194440e-4f, p);
    r = r + f;
    r = fmaf(ef, 0.693359375f, r);
    return r;
}

// ---------------------------------------------------------------------------
// fp16 2-way exact-residual splits
// ---------------------------------------------------------------------------
__device__ __forceinline__ void split2(float v, __half& h0, __half& h1) {
    h0 = __float2half_rn(v);
    h1 = __float2half_rn(v - __half2float(h0));
}

__global__ __launch_bounds__(1024) void split_a_kernel(const float* __restrict__ A) {
    size_t i = (size_t)blockIdx.x * blockDim.x + threadIdx.x;  // float4 index
    float4 x = reinterpret_cast<const float4*>(A)[i];
    float v[4] = {x.x, x.y, x.z, x.w};
    __half h0[4], h1[4];
#pragma unroll
    for (int c = 0; c < 4; c++) split2(v[c], h0[c], h1[c]);
    __half2* p0 = reinterpret_cast<__half2*>(g_A0);
    __half2* p1 = reinterpret_cast<__half2*>(g_A1);
    p0[2 * i]     = __half2(h0[0], h0[1]);
    p0[2 * i + 1] = __half2(h0[2], h0[3]);
    p1[2 * i]     = __half2(h1[0], h1[1]);
    p1[2 * i + 1] = __half2(h1[2], h1[3]);
}

// W[k][n] -> B[n][k]; also zeroes g_marginal (fused init)
__global__ __launch_bounds__(512) void split_b_kernel(const float* __restrict__ W) {
    int n = blockIdx.x;       // 0..639
    int k = threadIdx.x;      // 0..511
    if (k == 0) g_marginal[n] = 0.0f;
    float v = W[(size_t)k * GVDIM + n];
    __half h0, h1;
    split2(v, h0, h1);
    g_B0[(size_t)n * H_DIM + k] = h0;
    g_B1[(size_t)n * H_DIM + k] = h1;
}

// ---------------------------------------------------------------------------
// GEMM (R5 form): logits = A*W + b, 3-term fp16 split (a0b0+a0b1+a1b0).
// BM=128, BN=128, BK=32; 256 threads; warp tile 64x32.
// Double-buffered smem, 80B padded rows, ONE sync per stage.
// ---------------------------------------------------------------------------
#define STG_BYTES   40960
#define SPLIT_BYTES 10240
#define SMEM_BYTES  (2 * STG_BYTES)

__global__ __launch_bounds__(256, 2) void gemm_kernel(const float* __restrict__ bias) {
    extern __shared__ char smem[];
    const uint32_t sb = smem_u32(smem);
    const int tid  = threadIdx.x;
    const int wid  = tid >> 5;
    const int lane = tid & 31;
    const int wm = wid >> 2;
    const int wn = wid & 3;
    const int m0 = blockIdx.y * 128;
    const int n0 = blockIdx.x * 128;

    float acc[4][4][4];
#pragma unroll
    for (int mf = 0; mf < 4; mf++)
#pragma unroll
        for (int nf = 0; nf < 4; nf++)
#pragma unroll
            for (int c = 0; c < 4; c++) acc[mf][nf][c] = 0.0f;

    const int r0 = tid >> 2;
    const int kc = tid & 3;
    const __half* pA0 = g_A0 + (size_t)(m0 + r0) * H_DIM + kc * 8;
    const __half* pA1 = g_A1 + (size_t)(m0 + r0) * H_DIM + kc * 8;
    const __half* pB0 = g_B0 + (size_t)(n0 + r0) * H_DIM + kc * 8;
    const __half* pB1 = g_B1 + (size_t)(n0 + r0) * H_DIM + kc * 8;
    const uint32_t sA = sb + r0 * 80 + kc * 16;
    const size_t ROW64 = (size_t)64 * H_DIM;

    auto issue_stage = [&](int s) {
        const int off = s * 32;
        const uint32_t buf = (uint32_t)(s & 1) * STG_BYTES;
        cp_async16(sA + buf,                      pA0 + off);
        cp_async16(sA + buf + 5120,               pA0 + off + ROW64);
        cp_async16(sA + buf + SPLIT_BYTES,        pA1 + off);
        cp_async16(sA + buf + SPLIT_BYTES + 5120, pA1 + off + ROW64);
        cp_async16(sA + buf + 20480,              pB0 + off);
        cp_async16(sA + buf + 20480 + 5120,       pB0 + off + ROW64);
        cp_async16(sA + buf + 30720,              pB1 + off);
        cp_async16(sA + buf + 30720 + 5120,       pB1 + off + ROW64);
        asm volatile("cp.async.commit_group;" ::: "memory");
    };

    issue_stage(0);

    const int a_row = wm * 64 + (lane & 15);
    const int a_kc  = (lane >> 4) * 16;
    const int b_row = wn * 32 + ((lane >> 4) & 1) * 8 + (lane & 7);
    const int b_kc  = ((lane >> 3) & 1) * 16;

    for (int s = 0; s < 16; s++) {
        asm volatile("cp.async.wait_group 0;" ::: "memory");
        __syncthreads();
        if (s + 1 < 16) issue_stage(s + 1);

        const uint32_t abase = sb + (s & 1) * STG_BYTES;
        const uint32_t bbase = abase + 20480;

#pragma unroll
        for (int ks = 0; ks < 2; ks++) {
            uint32_t Bf[2][8];
#pragma unroll
            for (int s2 = 0; s2 < 2; s2++)
#pragma unroll
                for (int p = 0; p < 2; p++)
                    ldsm4(&Bf[s2][p * 4], bbase + s2 * SPLIT_BYTES +
                          (b_row + p * 16) * 80 + ks * 32 + b_kc);

            uint32_t Af[4][4];
#pragma unroll
            for (int mf = 0; mf < 4; mf++)
                ldsm4(Af[mf], abase + (a_row + mf * 16) * 80 + ks * 32 + a_kc);
#pragma unroll
            for (int mf = 0; mf < 4; mf++)
#pragma unroll
                for (int nf = 0; nf < 4; nf++)
                    mma16816(acc[mf][nf], Af[mf], &Bf[0][nf * 2]);
#pragma unroll
            for (int mf = 0; mf < 4; mf++)
#pragma unroll
                for (int nf = 0; nf < 4; nf++)
                    mma16816(acc[mf][nf], Af[mf], &Bf[1][nf * 2]);
#pragma unroll
            for (int mf = 0; mf < 4; mf++)
                ldsm4(Af[mf], abase + SPLIT_BYTES + (a_row + mf * 16) * 80 + ks * 32 + a_kc);
#pragma unroll
            for (int mf = 0; mf < 4; mf++)
#pragma unroll
                for (int nf = 0; nf < 4; nf++)
                    mma16816(acc[mf][nf], Af[mf], &Bf[0][nf * 2]);
        }
    }

    const int gID = lane >> 2;
    const int tig = lane & 3;
    float2 bv[4];
#pragma unroll
    for (int nf = 0; nf < 4; nf++)
        bv[nf] = *reinterpret_cast<const float2*>(bias + n0 + wn * 32 + nf * 8 + tig * 2);

#pragma unroll
    for (int mf = 0; mf < 4; mf++) {
        const int m = m0 + wm * 64 + mf * 16 + gID;
#pragma unroll
        for (int nf = 0; nf < 4; nf++) {
            const int n = n0 + wn * 32 + nf * 8 + tig * 2;
            float2 v0 = {acc[mf][nf][0] + bv[nf].x, acc[mf][nf][1] + bv[nf].y};
            float2 v1 = {acc[mf][nf][2] + bv[nf].x, acc[mf][nf][3] + bv[nf].y};
            *reinterpret_cast<float2*>(g_logits + (size_t)m * GVDIM + n)       = v0;
            *reinterpret_cast<float2*>(g_logits + (size_t)(m + 8) * GVDIM + n) = v1;
        }
    }
}

// ---------------------------------------------------------------------------
// Epilogue: one warp per FRAME (both groups); 16 frames per warp; float4 loads.
// Element s=4j+c maps to v = 4*lane+128*j+c. Groups: j<2 -> g0; j=2 -> g=(lane>=16);
// j>2 -> g1. Approx-filter argmax (exact acc_logf only for candidates).
// ---------------------------------------------------------------------------
__global__ __launch_bounds__(256) void epilogue_kernel(
    const float* __restrict__ gumbel_u,
    const float* __restrict__ codevectors,
    float* __restrict__ out)
{
    const unsigned FULL = 0xffffffffu;
    __shared__ float smar[GVDIM];
    const int tid  = threadIdx.x;
    const int warp = blockIdx.x * 8 + (tid >> 5);
    const int lane = tid & 31;
    const bool cross = lane >= 16;       // group of j==2 elements for this lane

    for (int i = tid; i < GVDIM; i += 256) smar[i] = 0.0f;
    __syncthreads();

    float macc[20];
#pragma unroll
    for (int s = 0; s < 20; s++) macc[s] = 0.0f;

    const int f0 = warp * 16;
    for (int i = 0; i < 16; i++) {
        const int n = f0 + i;
        const float* lrow = g_logits + (size_t)n * GVDIM;
        const float* urow = gumbel_u + (size_t)n * GVDIM;

        float l[20], u[20], za[20];
#pragma unroll
        for (int j = 0; j < 5; j++) {
            const int e0 = 4 * lane + 128 * j;
            float4 lf = *reinterpret_cast<const float4*>(lrow + e0);
            float4 uf = *reinterpret_cast<const float4*>(urow + e0);
            l[4*j] = lf.x; l[4*j+1] = lf.y; l[4*j+2] = lf.z; l[4*j+3] = lf.w;
            u[4*j] = uf.x; u[4*j+1] = uf.y; u[4*j+2] = uf.z; u[4*j+3] = uf.w;
        }

        // ---- approx pass ----
        float lmax0 = -3.4e38f, lmax1 = -3.4e38f;
        float zax0  = -3.4e38f, zax1  = -3.4e38f;
#pragma unroll
        for (int s = 0; s < 20; s++) {
            const int j = s >> 2;
            const float t  = -__logf(u[s]);
            const float zv = l[s] - __logf(t);
            za[s] = zv;
            const bool g1 = (j > 2) || (j == 2 && cross);
            if (g1) {
                lmax1 = fmaxf(lmax1, l[s]);
                if (u[s] <= 0.99f) zax1 = fmaxf(zax1, zv);
            } else {
                lmax0 = fmaxf(lmax0, l[s]);
                if (u[s] <= 0.99f) zax0 = fmaxf(zax0, zv);
            }
        }
#pragma unroll
        for (int off = 16; off; off >>= 1) {
            lmax0 = fmaxf(lmax0, __shfl_xor_sync(FULL, lmax0, off));
            lmax1 = fmaxf(lmax1, __shfl_xor_sync(FULL, lmax1, off));
            zax0  = fmaxf(zax0,  __shfl_xor_sync(FULL, zax0,  off));
            zax1  = fmaxf(zax1,  __shfl_xor_sync(FULL, zax1,  off));
        }
        const float th0 = zax0 - 1e-3f;
        const float th1 = zax1 - 1e-3f;

        // ---- exact pass for candidates ----
        float zb0 = -3.4e38f, zb1 = -3.4e38f;
        int   ib0 = 0x7fffffff, ib1 = 0x7fffffff;
#pragma unroll
        for (int s = 0; s < 20; s++) {
            const int j = s >> 2;
            const int c = s & 3;
            const int v = 4 * lane + 128 * j + c;
            const bool g1 = (j > 2) || (j == 2 && cross);
            const float th = g1 ? th1 : th0;
            if (u[s] > 0.99f || za[s] >= th) {
                const float te = -acc_logf(u[s]);
                const float zv = l[s] - acc_logf(te);
                if (g1) {
                    const int vg = v - VNUM;
                    if (zv > zb1 || (zv == zb1 && vg < ib1)) { zb1 = zv; ib1 = vg; }
                } else {
                    if (zv > zb0 || (zv == zb0 && v < ib0)) { zb0 = zv; ib0 = v; }
                }
            }
        }
#pragma unroll
        for (int off = 16; off; off >>= 1) {
            const float z0 = __shfl_xor_sync(FULL, zb0, off);
            const int   i0 = __shfl_xor_sync(FULL, ib0, off);
            if (z0 > zb0 || (z0 == zb0 && i0 < ib0)) { zb0 = z0; ib0 = i0; }
            const float z1 = __shfl_xor_sync(FULL, zb1, off);
            const int   i1 = __shfl_xor_sync(FULL, ib1, off);
            if (z1 > zb1 || (z1 == zb1 && i1 < ib1)) { zb1 = z1; ib1 = i1; }
        }

        // ---- noise-free softmax -> marginal partials ----
        float e[20];
        float s0 = 0.0f, s1 = 0.0f;
#pragma unroll
        for (int s = 0; s < 20; s++) {
            const int j = s >> 2;
            const bool g1 = (j > 2) || (j == 2 && cross);
            const float lm = g1 ? lmax1 : lmax0;
            e[s] = __expf(l[s] - lm);
            if (g1) s1 += e[s]; else s0 += e[s];
        }
#pragma unroll
        for (int off = 16; off; off >>= 1) {
            s0 += __shfl_xor_sync(FULL, s0, off);
            s1 += __shfl_xor_sync(FULL, s1, off);
        }
        const float rs0 = 1.0f / s0;
        const float rs1 = 1.0f / s1;
#pragma unroll
        for (int s = 0; s < 20; s++) {
            const int j = s >> 2;
            const bool g1 = (j > 2) || (j == 2 && cross);
            macc[s] = fmaf(e[s], g1 ? rs1 : rs0, macc[s]);
        }

        // ---- codes gather: both groups ----
        const float4* cv0 = reinterpret_cast<const float4*>(
            codevectors + (size_t)ib0 * DDIM);
        const float4* cv1 = reinterpret_cast<const float4*>(
            codevectors + (size_t)(VNUM + ib1) * DDIM);
        float4* op = reinterpret_cast<float4*>(out + (size_t)n * 256);
        op[lane]      = cv0[lane];
        op[32 + lane] = cv1[lane];
    }

    // block-level marginal reduction, then few global atomics
#pragma unroll
    for (int s = 0; s < 20; s++) {
        const int j = s >> 2;
        const int c = s & 3;
        const int v = 4 * lane + 128 * j + c;
        atomicAdd(&smar[v], macc[s]);
    }
    __syncthreads();
    for (int i = tid; i < GVDIM; i += 256)
        atomicAdd(&g_marginal[i], smar[i]);
}

// ---------------------------------------------------------------------------
__global__ void perp_kernel(float* __restrict__ out, int out_size) {
    __shared__ float red[2];
    const int i    = threadIdx.x;          // 0..639
    const int lane = i & 31;
    if (i < 2) red[i] = 0.0f;
    __syncthreads();
    const float m = g_marginal[i] * (1.0f / (float)N_FRAMES);
    float part = m * acc_logf(m + 1e-7f);
#pragma unroll
    for (int off = 16; off; off >>= 1)
        part += __shfl_xor_sync(0xffffffffu, part, off);
    if (lane == 0) atomicAdd(&red[i >= VNUM ? 1 : 0], part);
    __syncthreads();
    if (i == 0) {
        const float perp = __expf(-red[0]) + __expf(-red[1]);
        if (out_size > N_FRAMES * 256) out[(size_t)N_FRAMES * 256] = perp;
    }
}

// ---------------------------------------------------------------------------
extern "C" void kernel_launch(void* const* d_in, const int* in_sizes, int n_in,
                              void* d_out, int out_size) {
    const float* hs = (const float*)d_in[0];   // [16,4096,512]
    const float* W  = (const float*)d_in[1];   // [512,640]
    const float* b  = (const float*)d_in[2];   // [640]
    const float* cv = (const float*)d_in[3];   // [640,128]
    const float* gu = (const float*)d_in[4];   // [131072,320]
    float* out = (float*)d_out;

    split_b_kernel<<<GVDIM, 512>>>(W);
    split_a_kernel<<<8192, 1024>>>(hs);

    cudaFuncSetAttribute(gemm_kernel,
                         cudaFuncAttributeMaxDynamicSharedMemorySize, SMEM_BYTES);
    gemm_kernel<<<dim3(5, 512), 256, SMEM_BYTES>>>(b);

    epilogue_kernel<<<512, 256>>>(gu, cv, out);
    perp_kernel<<<1, GVDIM>>>(out, out_size);
}

// round 8
// speedup vs baseline: 1.1912x; 1.0717x over previous
#include <cuda_runtime.h>
#include <cuda_fp16.h>
#include <cstdint>

#define N_FRAMES 65536
#define H_DIM    512
#define GVDIM    640
#define VNUM     320
#define DDIM     128

// --------------------------- device scratch --------------------------------
__device__ float g_logits[(size_t)N_FRAMES * GVDIM];   // 160 MiB
__device__ float g_marginal[GVDIM];
__device__ __half g_A0[(size_t)N_FRAMES * H_DIM];      // 64 MiB
__device__ __half g_A1[(size_t)N_FRAMES * H_DIM];      // 64 MiB
__device__ __half g_B0[GVDIM * H_DIM];                 // W^T split hi [640][512]
__device__ __half g_B1[GVDIM * H_DIM];                 // W^T split lo

// --------------------------- helpers ---------------------------------------
__device__ __forceinline__ uint32_t smem_u32(const void* p) {
    uint32_t a;
    asm("{ .reg .u64 t; cvta.to.shared.u64 t, %1; cvt.u32.u64 %0, t; }"
        : "=r"(a) : "l"(p));
    return a;
}

__device__ __forceinline__ void cp_async16(uint32_t saddr, const void* gaddr) {
    asm volatile("cp.async.cg.shared.global [%0], [%1], 16;"
                 :: "r"(saddr), "l"(gaddr) : "memory");
}

__device__ __forceinline__ void ldsm4(uint32_t r[4], uint32_t addr) {
    asm volatile("ldmatrix.sync.aligned.m8n8.x4.shared.b16 {%0,%1,%2,%3}, [%4];"
                 : "=r"(r[0]), "=r"(r[1]), "=r"(r[2]), "=r"(r[3]) : "r"(addr));
}

__device__ __forceinline__ void mma16816(float c[4], const uint32_t a[4],
                                         const uint32_t b[2]) {
    asm volatile(
        "mma.sync.aligned.m16n8k16.row.col.f32.f16.f16.f32 "
        "{%0,%1,%2,%3}, {%4,%5,%6,%7}, {%8,%9}, {%0,%1,%2,%3};"
        : "+f"(c[0]), "+f"(c[1]), "+f"(c[2]), "+f"(c[3])
        : "r"(a[0]), "r"(a[1]), "r"(a[2]), "r"(a[3]), "r"(b[0]), "r"(b[1]));
}

// ---------------------------------------------------------------------------
// ~1-ulp log (fast-math proof)
// ---------------------------------------------------------------------------
__device__ __forceinline__ float acc_logf(float x) {
    int   ix = __float_as_int(x);
    int   e  = ((ix >> 23) & 0xff) - 126;
    float m  = __int_as_float((ix & 0x007fffff) | 0x3f000000);
    if (m < 0.70710678118654752f) { m += m; e -= 1; }
    float f = m - 1.0f;
    float z = f * f;
    float p = 7.0376836292e-2f;
    p = fmaf(p, f, -1.1514610310e-1f);
    p = fmaf(p, f,  1.1676998740e-1f);
    p = fmaf(p, f, -1.2420140846e-1f);
    p = fmaf(p, f,  1.4249322787e-1f);
    p = fmaf(p, f, -1.6668057665e-1f);
    p = fmaf(p, f,  2.0000714765e-1f);
    p = fmaf(p, f, -2.4999993993e-1f);
    p = fmaf(p, f,  3.3333331174e-1f);
    p = p * f * z;
    float ef = (float)e;
    p = fmaf(-0.5f, z, p);
    float r = fmaf(ef, -2.12194440e-4f, p);
    r = r + f;
    r = fmaf(ef, 0.693359375f, r);
    return r;
}

// ---------------------------------------------------------------------------
// fp16 2-way exact-residual splits
// ---------------------------------------------------------------------------
__device__ __forceinline__ void split2(float v, __half& h0, __half& h1) {
    h0 = __float2half_rn(v);
    h1 = __float2half_rn(v - __half2float(h0));
}

__global__ __launch_bounds__(1024) void split_a_kernel(const float* __restrict__ A) {
    size_t i = (size_t)blockIdx.x * blockDim.x + threadIdx.x;  // float4 index
    float4 x = reinterpret_cast<const float4*>(A)[i];
    float v[4] = {x.x, x.y, x.z, x.w};
    __half h0[4], h1[4];
#pragma unroll
    for (int c = 0; c < 4; c++) split2(v[c], h0[c], h1[c]);
    __half2* p0 = reinterpret_cast<__half2*>(g_A0);
    __half2* p1 = reinterpret_cast<__half2*>(g_A1);
    p0[2 * i]     = __half2(h0[0], h0[1]);
    p0[2 * i + 1] = __half2(h0[2], h0[3]);
    p1[2 * i]     = __half2(h1[0], h1[1]);
    p1[2 * i + 1] = __half2(h1[2], h1[3]);
}

// W[k][n] -> B[n][k]; also zeroes g_marginal (fused init)
__global__ __launch_bounds__(512) void split_b_kernel(const float* __restrict__ W) {
    int n = blockIdx.x;       // 0..639
    int k = threadIdx.x;      // 0..511
    if (k == 0) g_marginal[n] = 0.0f;
    float v = W[(size_t)k * GVDIM + n];
    __half h0, h1;
    split2(v, h0, h1);
    g_B0[(size_t)n * H_DIM + k] = h0;
    g_B1[(size_t)n * H_DIM + k] = h1;
}

// ---------------------------------------------------------------------------
// GEMM (R5 form): logits = A*W + b, 3-term fp16 split (a0b0+a0b1+a1b0).
// BM=128, BN=128, BK=32; 256 threads; warp tile 64x32.
// Double-buffered smem, 80B padded rows, ONE sync per stage.
// ---------------------------------------------------------------------------
#define STG_BYTES   40960
#define SPLIT_BYTES 10240
#define SMEM_BYTES  (2 * STG_BYTES)

__global__ __launch_bounds__(256, 2) void gemm_kernel(const float* __restrict__ bias) {
    extern __shared__ char smem[];
    const uint32_t sb = smem_u32(smem);
    const int tid  = threadIdx.x;
    const int wid  = tid >> 5;
    const int lane = tid & 31;
    const int wm = wid >> 2;
    const int wn = wid & 3;
    const int m0 = blockIdx.y * 128;
    const int n0 = blockIdx.x * 128;

    float acc[4][4][4];
#pragma unroll
    for (int mf = 0; mf < 4; mf++)
#pragma unroll
        for (int nf = 0; nf < 4; nf++)
#pragma unroll
            for (int c = 0; c < 4; c++) acc[mf][nf][c] = 0.0f;

    const int r0 = tid >> 2;
    const int kc = tid & 3;
    const __half* pA0 = g_A0 + (size_t)(m0 + r0) * H_DIM + kc * 8;
    const __half* pA1 = g_A1 + (size_t)(m0 + r0) * H_DIM + kc * 8;
    const __half* pB0 = g_B0 + (size_t)(n0 + r0) * H_DIM + kc * 8;
    const __half* pB1 = g_B1 + (size_t)(n0 + r0) * H_DIM + kc * 8;
    const uint32_t sA = sb + r0 * 80 + kc * 16;
    const size_t ROW64 = (size_t)64 * H_DIM;

    auto issue_stage = [&](int s) {
        const int off = s * 32;
        const uint32_t buf = (uint32_t)(s & 1) * STG_BYTES;
        cp_async16(sA + buf,                      pA0 + off);
        cp_async16(sA + buf + 5120,               pA0 + off + ROW64);
        cp_async16(sA + buf + SPLIT_BYTES,        pA1 + off);
        cp_async16(sA + buf + SPLIT_BYTES + 5120, pA1 + off + ROW64);
        cp_async16(sA + buf + 20480,              pB0 + off);
        cp_async16(sA + buf + 20480 + 5120,       pB0 + off + ROW64);
        cp_async16(sA + buf + 30720,              pB1 + off);
        cp_async16(sA + buf + 30720 + 5120,       pB1 + off + ROW64);
        asm volatile("cp.async.commit_group;" ::: "memory");
    };

    issue_stage(0);

    const int a_row = wm * 64 + (lane & 15);
    const int a_kc  = (lane >> 4) * 16;
    const int b_row = wn * 32 + ((lane >> 4) & 1) * 8 + (lane & 7);
    const int b_kc  = ((lane >> 3) & 1) * 16;

    for (int s = 0; s < 16; s++) {
        asm volatile("cp.async.wait_group 0;" ::: "memory");
        __syncthreads();
        if (s + 1 < 16) issue_stage(s + 1);

        const uint32_t abase = sb + (s & 1) * STG_BYTES;
        const uint32_t bbase = abase + 20480;

#pragma unroll
        for (int ks = 0; ks < 2; ks++) {
            uint32_t Bf[2][8];
#pragma unroll
            for (int s2 = 0; s2 < 2; s2++)
#pragma unroll
                for (int p = 0; p < 2; p++)
                    ldsm4(&Bf[s2][p * 4], bbase + s2 * SPLIT_BYTES +
                          (b_row + p * 16) * 80 + ks * 32 + b_kc);

            uint32_t Af[4][4];
#pragma unroll
            for (int mf = 0; mf < 4; mf++)
                ldsm4(Af[mf], abase + (a_row + mf * 16) * 80 + ks * 32 + a_kc);
#pragma unroll
            for (int mf = 0; mf < 4; mf++)
#pragma unroll
                for (int nf = 0; nf < 4; nf++)
                    mma16816(acc[mf][nf], Af[mf], &Bf[0][nf * 2]);
#pragma unroll
            for (int mf = 0; mf < 4; mf++)
#pragma unroll
                for (int nf = 0; nf < 4; nf++)
                    mma16816(acc[mf][nf], Af[mf], &Bf[1][nf * 2]);
#pragma unroll
            for (int mf = 0; mf < 4; mf++)
                ldsm4(Af[mf], abase + SPLIT_BYTES + (a_row + mf * 16) * 80 + ks * 32 + a_kc);
#pragma unroll
            for (int mf = 0; mf < 4; mf++)
#pragma unroll
                for (int nf = 0; nf < 4; nf++)
                    mma16816(acc[mf][nf], Af[mf], &Bf[0][nf * 2]);
        }
    }

    const int gID = lane >> 2;
    const int tig = lane & 3;
    float2 bv[4];
#pragma unroll
    for (int nf = 0; nf < 4; nf++)
        bv[nf] = *reinterpret_cast<const float2*>(bias + n0 + wn * 32 + nf * 8 + tig * 2);

#pragma unroll
    for (int mf = 0; mf < 4; mf++) {
        const int m = m0 + wm * 64 + mf * 16 + gID;
#pragma unroll
        for (int nf = 0; nf < 4; nf++) {
            const int n = n0 + wn * 32 + nf * 8 + tig * 2;
            float2 v0 = {acc[mf][nf][0] + bv[nf].x, acc[mf][nf][1] + bv[nf].y};
            float2 v1 = {acc[mf][nf][2] + bv[nf].x, acc[mf][nf][3] + bv[nf].y};
            *reinterpret_cast<float2*>(g_logits + (size_t)m * GVDIM + n)       = v0;
            *reinterpret_cast<float2*>(g_logits + (size_t)(m + 8) * GVDIM + n) = v1;
        }
    }
}

// ---------------------------------------------------------------------------
// Epilogue (R5 form, more blocks): one warp per (n,g) pair; 8 pairs per warp;
// 2048 blocks x 256 threads. Approx-filter argmax, exact only for candidates.
// ---------------------------------------------------------------------------
__global__ __launch_bounds__(256) void epilogue_kernel(
    const float* __restrict__ gumbel_u,
    const float* __restrict__ codevectors,
    float* __restrict__ out)
{
    const unsigned FULL = 0xffffffffu;
    __shared__ float smar[GVDIM];
    const int tid  = threadIdx.x;
    const int warp = blockIdx.x * 8 + (tid >> 5);
    const int lane = tid & 31;

    for (int i = tid; i < GVDIM; i += 256) smar[i] = 0.0f;
    __syncthreads();

    float macc[2][10];
#pragma unroll
    for (int g = 0; g < 2; g++)
#pragma unroll
        for (int j = 0; j < 10; j++) macc[g][j] = 0.0f;

    const int p0 = warp * 8;
    for (int i = 0; i < 8; i++) {
        const int p = p0 + i;
        const int n = p >> 1;
        const int g = p & 1;
        const float* lrow = g_logits + (size_t)n * GVDIM + g * VNUM;
        const float* urow = gumbel_u + (size_t)p * VNUM;

        float l[10], u[10], za[10];
#pragma unroll
        for (int jj = 0; jj < 5; jj++) {
            const int e0 = 2 * (lane + 32 * jj);
            float2 lf = *reinterpret_cast<const float2*>(lrow + e0);
            float2 uf = *reinterpret_cast<const float2*>(urow + e0);
            l[2 * jj] = lf.x; l[2 * jj + 1] = lf.y;
            u[2 * jj] = uf.x; u[2 * jj + 1] = uf.y;
        }

        float lmax = -3.4e38f, zax = -3.4e38f;
#pragma unroll
        for (int s = 0; s < 10; s++) {
            lmax = fmaxf(lmax, l[s]);
            const float t  = -__logf(u[s]);
            const float zv = l[s] - __logf(t);
            za[s] = zv;
            if (u[s] <= 0.99f) zax = fmaxf(zax, zv);
        }
#pragma unroll
        for (int off = 16; off; off >>= 1) {
            lmax = fmaxf(lmax, __shfl_xor_sync(FULL, lmax, off));
            zax  = fmaxf(zax,  __shfl_xor_sync(FULL, zax,  off));
        }
        const float thresh = zax - 1e-3f;

        float zbest = -3.4e38f;
        int   ibest = 0x7fffffff;
#pragma unroll
        for (int jj = 0; jj < 5; jj++)
#pragma unroll
            for (int q = 0; q < 2; q++) {
                const int s = 2 * jj + q;
                if (u[s] > 0.99f || za[s] >= thresh) {
                    const float te = -acc_logf(u[s]);
                    const float zv = l[s] - acc_logf(te);
                    const int v = 64 * jj + 2 * lane + q;
                    if (zv > zbest || (zv == zbest && v < ibest)) { zbest = zv; ibest = v; }
                }
            }
#pragma unroll
        for (int off = 16; off; off >>= 1) {
            const float zo = __shfl_xor_sync(FULL, zbest, off);
            const int   io = __shfl_xor_sync(FULL, ibest, off);
            if (zo > zbest || (zo == zbest && io < ibest)) { zbest = zo; ibest = io; }
        }

        float e[10];
        float ssum = 0.0f;
#pragma unroll
        for (int s = 0; s < 10; s++) { e[s] = __expf(l[s] - lmax); ssum += e[s]; }
#pragma unroll
        for (int off = 16; off; off >>= 1)
            ssum += __shfl_xor_sync(FULL, ssum, off);
        const float rs = 1.0f / ssum;
#pragma unroll
        for (int s = 0; s < 10; s++) macc[g][s] = fmaf(e[s], rs, macc[g][s]);

        const float4* cvp = reinterpret_cast<const float4*>(
            codevectors + ((size_t)(g * VNUM + ibest)) * DDIM);
        float4* op = reinterpret_cast<float4*>(out + (size_t)n * 256 + g * DDIM);
        op[lane] = cvp[lane];
    }

#pragma unroll
    for (int g = 0; g < 2; g++)
#pragma unroll
        for (int jj = 0; jj < 5; jj++)
#pragma unroll
            for (int q = 0; q < 2; q++)
                atomicAdd(&smar[g * VNUM + 64 * jj + 2 * lane + q], macc[g][2 * jj + q]);
    __syncthreads();
    for (int i = tid; i < GVDIM; i += 256)
        atomicAdd(&g_marginal[i], smar[i]);
}

// ---------------------------------------------------------------------------
__global__ void perp_kernel(float* __restrict__ out, int out_size) {
    __shared__ float red[2];
    const int i    = threadIdx.x;          // 0..639
    const int lane = i & 31;
    if (i < 2) red[i] = 0.0f;
    __syncthreads();
    const float m = g_marginal[i] * (1.0f / (float)N_FRAMES);
    float part = m * acc_logf(m + 1e-7f);
#pragma unroll
    for (int off = 16; off; off >>= 1)
        part += __shfl_xor_sync(0xffffffffu, part, off);
    if (lane == 0) atomicAdd(&red[i >= VNUM ? 1 : 0], part);
    __syncthreads();
    if (i == 0) {
        const float perp = __expf(-red[0]) + __expf(-red[1]);
        if (out_size > N_FRAMES * 256) out[(size_t)N_FRAMES * 256] = perp;
    }
}

// ---------------------------------------------------------------------------
extern "C" void kernel_launch(void* const* d_in, const int* in_sizes, int n_in,
                              void* d_out, int out_size) {
    const float* hs = (const float*)d_in[0];   // [16,4096,512]
    const float* W  = (const float*)d_in[1];   // [512,640]
    const float* b  = (const float*)d_in[2];   // [640]
    const float* cv = (const float*)d_in[3];   // [640,128]
    const float* gu = (const float*)d_in[4];   // [131072,320]
    float* out = (float*)d_out;

    split_b_kernel<<<GVDIM, 512>>>(W);
    split_a_kernel<<<8192, 1024>>>(hs);

    cudaFuncSetAttribute(gemm_kernel,
                         cudaFuncAttributeMaxDynamicSharedMemorySize, SMEM_BYTES);
    gemm_kernel<<<dim3(5, 512), 256, SMEM_BYTES>>>(b);

    epilogue_kernel<<<2048, 256>>>(gu, cv, out);
    perp_kernel<<<1, GVDIM>>>(out, out_size);
}